// round 1
// baseline (speedup 1.0000x reference)
#include <cuda_runtime.h>
#include <cuda_bf16.h>

#define NT 4096
#define D  128
#define H  8

// ---------------- scratch (device globals; no allocs allowed) ----------------
__device__ float g_q[H * NT * D];
__device__ float g_k[H * NT * D];
__device__ float g_v[H * NT * D];
__device__ float g_o[H * NT * D];
__device__ float g_wgT[D * D];

// ---------------- kernel 1: q/k/v projections -------------------------------
// grid (NT/64, H, 3), block 256.  out[64x128] = x[64x128] @ W[128x128]
__global__ void __launch_bounds__(256) qkv_kernel(const float* __restrict__ x,
                                                  const float* __restrict__ Wk,
                                                  const float* __restrict__ Wq,
                                                  const float* __restrict__ Wv) {
    __shared__ float xs[64][D];    // 32KB
    __shared__ float Ws[16][D];    // 8KB
    const int tile  = blockIdx.x;
    const int h     = blockIdx.y;
    const int which = blockIdx.z;  // 0=q,1=k,2=v
    const float* W = (which == 0 ? Wq : which == 1 ? Wk : Wv) + (size_t)h * D * D;
    float* out = (which == 0 ? g_q : which == 1 ? g_k : g_v)
                 + (size_t)h * NT * D + (size_t)tile * 64 * D;
    const int tid = threadIdx.x;

    for (int it = tid; it < 64 * 32; it += 256) {
        int r = it >> 5, c4 = it & 31;
        *(float4*)&xs[r][c4 * 4] =
            *(const float4*)(x + (size_t)(tile * 64 + r) * D + c4 * 4);
    }
    const int ty = tid >> 4, tx = tid & 15;
    float acc[4][8];
#pragma unroll
    for (int i = 0; i < 4; i++)
#pragma unroll
        for (int j = 0; j < 8; j++) acc[i][j] = 0.f;

    for (int fc = 0; fc < 8; fc++) {
        __syncthreads();
        for (int it = tid; it < 16 * 32; it += 256) {
            int r = it >> 5, c4 = it & 31;
            *(float4*)&Ws[r][c4 * 4] =
                *(const float4*)(W + (size_t)(fc * 16 + r) * D + c4 * 4);
        }
        __syncthreads();
#pragma unroll
        for (int f = 0; f < 16; f++) {
            float a[4];
#pragma unroll
            for (int ii = 0; ii < 4; ii++) a[ii] = xs[ty * 4 + ii][fc * 16 + f];
            float4 b0 = *(float4*)&Ws[f][tx * 8];
            float4 b1 = *(float4*)&Ws[f][tx * 8 + 4];
            float b[8] = {b0.x, b0.y, b0.z, b0.w, b1.x, b1.y, b1.z, b1.w};
#pragma unroll
            for (int ii = 0; ii < 4; ii++)
#pragma unroll
                for (int jj = 0; jj < 8; jj++)
                    acc[ii][jj] = fmaf(a[ii], b[jj], acc[ii][jj]);
        }
    }
#pragma unroll
    for (int ii = 0; ii < 4; ii++) {
        float4 s0 = make_float4(acc[ii][0], acc[ii][1], acc[ii][2], acc[ii][3]);
        float4 s1 = make_float4(acc[ii][4], acc[ii][5], acc[ii][6], acc[ii][7]);
        *(float4*)(out + (size_t)(ty * 4 + ii) * D + tx * 8)     = s0;
        *(float4*)(out + (size_t)(ty * 4 + ii) * D + tx * 8 + 4) = s1;
    }
}

// ---------------- kernel 2: flash attention (fp32) --------------------------
// grid (NT/64, H), block 256, dynamic smem.
// Layout (floats): QsT[128][68] | KsT[128][68] | Vs[64][128] | PsT[64][68]
#define QKT_LD 68
#define ATTN_SMEM_FLOATS (128 * QKT_LD + 128 * QKT_LD + 64 * 128 + 64 * QKT_LD)
#define ATTN_SMEM_BYTES  (ATTN_SMEM_FLOATS * 4)

__global__ void __launch_bounds__(256) attn_kernel(const float* __restrict__ W_m) {
    extern __shared__ float sm[];
    float* QsT = sm;                          // [128][68]  QsT[d][i]
    float* KsT = QsT + 128 * QKT_LD;          // [128][68]  KsT[d][j]
    float* Vs  = KsT + 128 * QKT_LD;          // [64][128]  Vs[j][d]
    float* PsT = Vs + 64 * 128;               // [64][68]   PsT[j][i]

    const int h  = blockIdx.y;
    const int q0 = blockIdx.x * 64;
    const float* qg = g_q + (size_t)h * NT * D;
    const float* kg = g_k + (size_t)h * NT * D;
    const float* vg = g_v + (size_t)h * NT * D;

    const int tid = threadIdx.x;
    const int ty = tid >> 4, tx = tid & 15;   // i0 = 4*ty, j0 = 4*tx, d0 = 8*tx

    // load Q transposed: QsT[d][i] = q[q0+i][d]   (conflict-free scalar STS)
    for (int it = tid; it < 64 * 32; it += 256) {
        int i = it & 63, c4 = it >> 6;
        float4 v = *(const float4*)(qg + (size_t)(q0 + i) * D + c4 * 4);
        QsT[(c4 * 4 + 0) * QKT_LD + i] = v.x;
        QsT[(c4 * 4 + 1) * QKT_LD + i] = v.y;
        QsT[(c4 * 4 + 2) * QKT_LD + i] = v.z;
        QsT[(c4 * 4 + 3) * QKT_LD + i] = v.w;
    }

    float o[4][8];
#pragma unroll
    for (int i = 0; i < 4; i++)
#pragma unroll
        for (int j = 0; j < 8; j++) o[i][j] = 0.f;
    float m[4] = {-1e30f, -1e30f, -1e30f, -1e30f};
    float l[4] = {0.f, 0.f, 0.f, 0.f};

    for (int kb = 0; kb < NT / 64; kb++) {
        const int k0 = kb * 64;
        __syncthreads();   // prior PV reads of KsT/Vs/PsT done (also covers Q load, kb=0)
        // K transposed
        for (int it = tid; it < 64 * 32; it += 256) {
            int j = it & 63, c4 = it >> 6;
            float4 v = *(const float4*)(kg + (size_t)(k0 + j) * D + c4 * 4);
            KsT[(c4 * 4 + 0) * QKT_LD + j] = v.x;
            KsT[(c4 * 4 + 1) * QKT_LD + j] = v.y;
            KsT[(c4 * 4 + 2) * QKT_LD + j] = v.z;
            KsT[(c4 * 4 + 3) * QKT_LD + j] = v.w;
        }
        // V row-major (coalesced)
        for (int it = tid; it < 64 * 32; it += 256) {
            int j = it >> 5, c4 = it & 31;
            *(float4*)&Vs[j * 128 + c4 * 4] =
                *(const float4*)(vg + (size_t)(k0 + j) * D + c4 * 4);
        }
        __syncthreads();

        // ---- S = Q Kᵀ  (4x4 per thread) ----
        float s[4][4];
#pragma unroll
        for (int i = 0; i < 4; i++)
#pragma unroll
            for (int j = 0; j < 4; j++) s[i][j] = 0.f;
#pragma unroll 8
        for (int d = 0; d < D; d++) {
            float4 a = *(float4*)&QsT[d * QKT_LD + 4 * ty];
            float4 b = *(float4*)&KsT[d * QKT_LD + 4 * tx];
            float av[4] = {a.x, a.y, a.z, a.w};
            float bv[4] = {b.x, b.y, b.z, b.w};
#pragma unroll
            for (int i = 0; i < 4; i++)
#pragma unroll
                for (int j = 0; j < 4; j++)
                    s[i][j] = fmaf(av[i], bv[j], s[i][j]);
        }

        // ---- online softmax (rows i owned by the 16-lane tx group) ----
        float corr[4];
#pragma unroll
        for (int ii = 0; ii < 4; ii++) {
            float mx = fmaxf(fmaxf(s[ii][0], s[ii][1]), fmaxf(s[ii][2], s[ii][3]));
#pragma unroll
            for (int off = 8; off >= 1; off >>= 1)
                mx = fmaxf(mx, __shfl_xor_sync(0xffffffffu, mx, off, 16));
            float mnew = fmaxf(m[ii], mx);
            corr[ii] = __expf(m[ii] - mnew);
            m[ii] = mnew;
            float ps = 0.f;
#pragma unroll
            for (int jj = 0; jj < 4; jj++) {
                s[ii][jj] = __expf(s[ii][jj] - mnew);
                ps += s[ii][jj];
            }
#pragma unroll
            for (int off = 8; off >= 1; off >>= 1)
                ps += __shfl_xor_sync(0xffffffffu, ps, off, 16);
            l[ii] = l[ii] * corr[ii] + ps;
        }
        // write P transposed: PsT[j][i]
#pragma unroll
        for (int jj = 0; jj < 4; jj++) {
            float4 pv = make_float4(s[0][jj], s[1][jj], s[2][jj], s[3][jj]);
            *(float4*)&PsT[(4 * tx + jj) * QKT_LD + 4 * ty] = pv;
        }
        // rescale O
#pragma unroll
        for (int ii = 0; ii < 4; ii++)
#pragma unroll
            for (int dd = 0; dd < 8; dd++) o[ii][dd] *= corr[ii];
        __syncthreads();

        // ---- O += P V ----
#pragma unroll 4
        for (int j = 0; j < 64; j++) {
            float4 pp = *(float4*)&PsT[j * QKT_LD + 4 * ty];
            float4 v0 = *(float4*)&Vs[j * 128 + 8 * tx];
            float4 v1 = *(float4*)&Vs[j * 128 + 8 * tx + 4];
            float pv[4] = {pp.x, pp.y, pp.z, pp.w};
            float vv[8] = {v0.x, v0.y, v0.z, v0.w, v1.x, v1.y, v1.z, v1.w};
#pragma unroll
            for (int ii = 0; ii < 4; ii++)
#pragma unroll
                for (int dd = 0; dd < 8; dd++)
                    o[ii][dd] = fmaf(pv[ii], vv[dd], o[ii][dd]);
        }
    }

    // epilogue: O/l * W_m[h] -> g_o
    const float wm = W_m[h];
    float* og = g_o + (size_t)h * NT * D;
#pragma unroll
    for (int ii = 0; ii < 4; ii++) {
        float inv = wm / l[ii];
        float4 s0 = make_float4(o[ii][0] * inv, o[ii][1] * inv,
                                o[ii][2] * inv, o[ii][3] * inv);
        float4 s1 = make_float4(o[ii][4] * inv, o[ii][5] * inv,
                                o[ii][6] * inv, o[ii][7] * inv);
        size_t row = (size_t)(q0 + 4 * ty + ii) * D;
        *(float4*)(og + row + 8 * tx)     = s0;
        *(float4*)(og + row + 8 * tx + 4) = s1;
    }
}

// ---------------- kernel 2.5: transpose Wg ----------------------------------
__global__ void wgT_kernel(const float* __restrict__ Wg) {
    for (int it = threadIdx.x; it < D * D; it += blockDim.x) {
        int d = it >> 7, f = it & 127;
        g_wgT[f * D + d] = Wg[d * D + f];
    }
}

// ---------------- kernel 3: y = x + relu((x + sum_h o) @ WgT + bg) ----------
__global__ void __launch_bounds__(256) final_kernel(const float* __restrict__ x,
                                                    const float* __restrict__ bg,
                                                    float* __restrict__ y) {
    __shared__ float hs[64][D];    // 32KB
    __shared__ float Ws[16][D];    // 8KB
    __shared__ float bsh[D];
    const int n0 = blockIdx.x * 64;
    const int tid = threadIdx.x;

    for (int it = tid; it < 64 * 32; it += 256) {
        int r = it >> 5, c4 = it & 31;
        size_t off = (size_t)(n0 + r) * D + c4 * 4;
        float4 a = *(const float4*)(x + off);
#pragma unroll
        for (int hh = 0; hh < H; hh++) {
            float4 b = *(const float4*)(g_o + (size_t)hh * NT * D + off);
            a.x += b.x; a.y += b.y; a.z += b.z; a.w += b.w;
        }
        *(float4*)&hs[r][c4 * 4] = a;
    }
    if (tid < D) bsh[tid] = bg[tid];

    const int ty = tid >> 4, tx = tid & 15;
    float acc[4][8];
#pragma unroll
    for (int i = 0; i < 4; i++)
#pragma unroll
        for (int j = 0; j < 8; j++) acc[i][j] = 0.f;

    for (int fc = 0; fc < 8; fc++) {
        __syncthreads();
        for (int it = tid; it < 16 * 32; it += 256) {
            int r = it >> 5, c4 = it & 31;
            *(float4*)&Ws[r][c4 * 4] =
                *(const float4*)(g_wgT + (size_t)(fc * 16 + r) * D + c4 * 4);
        }
        __syncthreads();
#pragma unroll
        for (int f = 0; f < 16; f++) {
            float a[4];
#pragma unroll
            for (int ii = 0; ii < 4; ii++) a[ii] = hs[ty * 4 + ii][fc * 16 + f];
            float4 b0 = *(float4*)&Ws[f][tx * 8];
            float4 b1 = *(float4*)&Ws[f][tx * 8 + 4];
            float b[8] = {b0.x, b0.y, b0.z, b0.w, b1.x, b1.y, b1.z, b1.w};
#pragma unroll
            for (int ii = 0; ii < 4; ii++)
#pragma unroll
                for (int jj = 0; jj < 8; jj++)
                    acc[ii][jj] = fmaf(a[ii], b[jj], acc[ii][jj]);
        }
    }

#pragma unroll
    for (int ii = 0; ii < 4; ii++) {
        int n = n0 + ty * 4 + ii;
#pragma unroll
        for (int jj = 0; jj < 8; jj += 4) {
            int d = tx * 8 + jj;
            float4 xv = *(const float4*)(x + (size_t)n * D + d);
            float4 r;
            r.x = xv.x + fmaxf(acc[ii][jj + 0] + bsh[d + 0], 0.f);
            r.y = xv.y + fmaxf(acc[ii][jj + 1] + bsh[d + 1], 0.f);
            r.z = xv.z + fmaxf(acc[ii][jj + 2] + bsh[d + 2], 0.f);
            r.w = xv.w + fmaxf(acc[ii][jj + 3] + bsh[d + 3], 0.f);
            *(float4*)(y + (size_t)n * D + d) = r;
        }
    }
}

// ---------------- launch ----------------------------------------------------
extern "C" void kernel_launch(void* const* d_in, const int* in_sizes, int n_in,
                              void* d_out, int out_size) {
    const float* x  = (const float*)d_in[0];
    const float* Wk = (const float*)d_in[1];
    const float* Wq = (const float*)d_in[2];
    const float* Wv = (const float*)d_in[3];
    const float* Wm = (const float*)d_in[4];
    const float* Wg = (const float*)d_in[5];
    const float* bg = (const float*)d_in[6];
    float* y = (float*)d_out;

    cudaFuncSetAttribute(attn_kernel, cudaFuncAttributeMaxDynamicSharedMemorySize,
                         ATTN_SMEM_BYTES);

    qkv_kernel<<<dim3(NT / 64, H, 3), 256>>>(x, Wk, Wq, Wv);
    attn_kernel<<<dim3(NT / 64, H), 256, ATTN_SMEM_BYTES>>>(Wm);
    wgT_kernel<<<1, 256>>>(Wg);
    final_kernel<<<NT / 64, 256>>>(x, bg, y);
}

// round 2
// speedup vs baseline: 1.0006x; 1.0006x over previous
#include <cuda_runtime.h>
#include <cuda_bf16.h>

#define NT 4096
#define D  128
#define H  8

// ---------------- scratch (device globals; no allocs allowed) ----------------
__device__ float g_q[H * NT * D];
__device__ float g_k[H * NT * D];
__device__ float g_v[H * NT * D];
__device__ float g_o[H * NT * D];
__device__ float g_wgT[D * D];

// ---------------- kernel 1: q/k/v projections -------------------------------
// grid (NT/64, H, 3), block 256.  out[64x128] = x[64x128] @ W[128x128]
__global__ void __launch_bounds__(256) qkv_kernel(const float* __restrict__ x,
                                                  const float* __restrict__ Wk,
                                                  const float* __restrict__ Wq,
                                                  const float* __restrict__ Wv) {
    __shared__ float xs[64][D];    // 32KB
    __shared__ float Ws[16][D];    // 8KB
    const int tile  = blockIdx.x;
    const int h     = blockIdx.y;
    const int which = blockIdx.z;  // 0=q,1=k,2=v
    const float* W = (which == 0 ? Wq : which == 1 ? Wk : Wv) + (size_t)h * D * D;
    float* out = (which == 0 ? g_q : which == 1 ? g_k : g_v)
                 + (size_t)h * NT * D + (size_t)tile * 64 * D;
    const int tid = threadIdx.x;

    for (int it = tid; it < 64 * 32; it += 256) {
        int r = it >> 5, c4 = it & 31;
        *(float4*)&xs[r][c4 * 4] =
            *(const float4*)(x + (size_t)(tile * 64 + r) * D + c4 * 4);
    }
    const int ty = tid >> 4, tx = tid & 15;
    float acc[4][8];
#pragma unroll
    for (int i = 0; i < 4; i++)
#pragma unroll
        for (int j = 0; j < 8; j++) acc[i][j] = 0.f;

    for (int fc = 0; fc < 8; fc++) {
        __syncthreads();
        for (int it = tid; it < 16 * 32; it += 256) {
            int r = it >> 5, c4 = it & 31;
            *(float4*)&Ws[r][c4 * 4] =
                *(const float4*)(W + (size_t)(fc * 16 + r) * D + c4 * 4);
        }
        __syncthreads();
#pragma unroll
        for (int f = 0; f < 16; f++) {
            float a[4];
#pragma unroll
            for (int ii = 0; ii < 4; ii++) a[ii] = xs[ty * 4 + ii][fc * 16 + f];
            float4 b0 = *(float4*)&Ws[f][tx * 8];
            float4 b1 = *(float4*)&Ws[f][tx * 8 + 4];
            float b[8] = {b0.x, b0.y, b0.z, b0.w, b1.x, b1.y, b1.z, b1.w};
#pragma unroll
            for (int ii = 0; ii < 4; ii++)
#pragma unroll
                for (int jj = 0; jj < 8; jj++)
                    acc[ii][jj] = fmaf(a[ii], b[jj], acc[ii][jj]);
        }
    }
#pragma unroll
    for (int ii = 0; ii < 4; ii++) {
        float4 s0 = make_float4(acc[ii][0], acc[ii][1], acc[ii][2], acc[ii][3]);
        float4 s1 = make_float4(acc[ii][4], acc[ii][5], acc[ii][6], acc[ii][7]);
        *(float4*)(out + (size_t)(ty * 4 + ii) * D + tx * 8)     = s0;
        *(float4*)(out + (size_t)(ty * 4 + ii) * D + tx * 8 + 4) = s1;
    }
}

// ---------------- kernel 2: flash attention (fp32) --------------------------
// grid (NT/64, H), block 256, dynamic smem.
// Layout (floats): QsT[128][68] | KsT[128][68] | Vs[64][128] | PsT[64][68]
#define QKT_LD 68
#define ATTN_SMEM_FLOATS (128 * QKT_LD + 128 * QKT_LD + 64 * 128 + 64 * QKT_LD)
#define ATTN_SMEM_BYTES  (ATTN_SMEM_FLOATS * 4)

__global__ void __launch_bounds__(256) attn_kernel(const float* __restrict__ W_m) {
    extern __shared__ float sm[];
    float* QsT = sm;                          // [128][68]  QsT[d][i]
    float* KsT = QsT + 128 * QKT_LD;          // [128][68]  KsT[d][j]
    float* Vs  = KsT + 128 * QKT_LD;          // [64][128]  Vs[j][d]
    float* PsT = Vs + 64 * 128;               // [64][68]   PsT[j][i]

    const int h  = blockIdx.y;
    const int q0 = blockIdx.x * 64;
    const float* qg = g_q + (size_t)h * NT * D;
    const float* kg = g_k + (size_t)h * NT * D;
    const float* vg = g_v + (size_t)h * NT * D;

    const int tid = threadIdx.x;
    const int ty = tid >> 4, tx = tid & 15;   // i0 = 4*ty, j0 = 4*tx, d0 = 8*tx

    // load Q transposed: QsT[d][i] = q[q0+i][d]   (conflict-free scalar STS)
    for (int it = tid; it < 64 * 32; it += 256) {
        int i = it & 63, c4 = it >> 6;
        float4 v = *(const float4*)(qg + (size_t)(q0 + i) * D + c4 * 4);
        QsT[(c4 * 4 + 0) * QKT_LD + i] = v.x;
        QsT[(c4 * 4 + 1) * QKT_LD + i] = v.y;
        QsT[(c4 * 4 + 2) * QKT_LD + i] = v.z;
        QsT[(c4 * 4 + 3) * QKT_LD + i] = v.w;
    }

    float o[4][8];
#pragma unroll
    for (int i = 0; i < 4; i++)
#pragma unroll
        for (int j = 0; j < 8; j++) o[i][j] = 0.f;
    float m[4] = {-1e30f, -1e30f, -1e30f, -1e30f};
    float l[4] = {0.f, 0.f, 0.f, 0.f};

    for (int kb = 0; kb < NT / 64; kb++) {
        const int k0 = kb * 64;
        __syncthreads();   // prior PV reads of KsT/Vs/PsT done (also covers Q load, kb=0)
        // K transposed
        for (int it = tid; it < 64 * 32; it += 256) {
            int j = it & 63, c4 = it >> 6;
            float4 v = *(const float4*)(kg + (size_t)(k0 + j) * D + c4 * 4);
            KsT[(c4 * 4 + 0) * QKT_LD + j] = v.x;
            KsT[(c4 * 4 + 1) * QKT_LD + j] = v.y;
            KsT[(c4 * 4 + 2) * QKT_LD + j] = v.z;
            KsT[(c4 * 4 + 3) * QKT_LD + j] = v.w;
        }
        // V row-major (coalesced)
        for (int it = tid; it < 64 * 32; it += 256) {
            int j = it >> 5, c4 = it & 31;
            *(float4*)&Vs[j * 128 + c4 * 4] =
                *(const float4*)(vg + (size_t)(k0 + j) * D + c4 * 4);
        }
        __syncthreads();

        // ---- S = Q Kᵀ  (4x4 per thread) ----
        float s[4][4];
#pragma unroll
        for (int i = 0; i < 4; i++)
#pragma unroll
            for (int j = 0; j < 4; j++) s[i][j] = 0.f;
#pragma unroll 8
        for (int d = 0; d < D; d++) {
            float4 a = *(float4*)&QsT[d * QKT_LD + 4 * ty];
            float4 b = *(float4*)&KsT[d * QKT_LD + 4 * tx];
            float av[4] = {a.x, a.y, a.z, a.w};
            float bv[4] = {b.x, b.y, b.z, b.w};
#pragma unroll
            for (int i = 0; i < 4; i++)
#pragma unroll
                for (int j = 0; j < 4; j++)
                    s[i][j] = fmaf(av[i], bv[j], s[i][j]);
        }

        // ---- online softmax (rows i owned by the 16-lane tx group) ----
        float corr[4];
#pragma unroll
        for (int ii = 0; ii < 4; ii++) {
            float mx = fmaxf(fmaxf(s[ii][0], s[ii][1]), fmaxf(s[ii][2], s[ii][3]));
#pragma unroll
            for (int off = 8; off >= 1; off >>= 1)
                mx = fmaxf(mx, __shfl_xor_sync(0xffffffffu, mx, off, 16));
            float mnew = fmaxf(m[ii], mx);
            corr[ii] = __expf(m[ii] - mnew);
            m[ii] = mnew;
            float ps = 0.f;
#pragma unroll
            for (int jj = 0; jj < 4; jj++) {
                s[ii][jj] = __expf(s[ii][jj] - mnew);
                ps += s[ii][jj];
            }
#pragma unroll
            for (int off = 8; off >= 1; off >>= 1)
                ps += __shfl_xor_sync(0xffffffffu, ps, off, 16);
            l[ii] = l[ii] * corr[ii] + ps;
        }
        // write P transposed: PsT[j][i]
#pragma unroll
        for (int jj = 0; jj < 4; jj++) {
            float4 pv = make_float4(s[0][jj], s[1][jj], s[2][jj], s[3][jj]);
            *(float4*)&PsT[(4 * tx + jj) * QKT_LD + 4 * ty] = pv;
        }
        // rescale O
#pragma unroll
        for (int ii = 0; ii < 4; ii++)
#pragma unroll
            for (int dd = 0; dd < 8; dd++) o[ii][dd] *= corr[ii];
        __syncthreads();

        // ---- O += P V ----
#pragma unroll 4
        for (int j = 0; j < 64; j++) {
            float4 pp = *(float4*)&PsT[j * QKT_LD + 4 * ty];
            float4 v0 = *(float4*)&Vs[j * 128 + 8 * tx];
            float4 v1 = *(float4*)&Vs[j * 128 + 8 * tx + 4];
            float pv[4] = {pp.x, pp.y, pp.z, pp.w};
            float vv[8] = {v0.x, v0.y, v0.z, v0.w, v1.x, v1.y, v1.z, v1.w};
#pragma unroll
            for (int ii = 0; ii < 4; ii++)
#pragma unroll
                for (int dd = 0; dd < 8; dd++)
                    o[ii][dd] = fmaf(pv[ii], vv[dd], o[ii][dd]);
        }
    }

    // epilogue: O/l * W_m[h] -> g_o
    const float wm = W_m[h];
    float* og = g_o + (size_t)h * NT * D;
#pragma unroll
    for (int ii = 0; ii < 4; ii++) {
        float inv = wm / l[ii];
        float4 s0 = make_float4(o[ii][0] * inv, o[ii][1] * inv,
                                o[ii][2] * inv, o[ii][3] * inv);
        float4 s1 = make_float4(o[ii][4] * inv, o[ii][5] * inv,
                                o[ii][6] * inv, o[ii][7] * inv);
        size_t row = (size_t)(q0 + 4 * ty + ii) * D;
        *(float4*)(og + row + 8 * tx)     = s0;
        *(float4*)(og + row + 8 * tx + 4) = s1;
    }
}

// ---------------- kernel 2.5: transpose Wg ----------------------------------
__global__ void wgT_kernel(const float* __restrict__ Wg) {
    for (int it = threadIdx.x; it < D * D; it += blockDim.x) {
        int d = it >> 7, f = it & 127;
        g_wgT[f * D + d] = Wg[d * D + f];
    }
}

// ---------------- kernel 3: y = x + relu((x + sum_h o) @ WgT + bg) ----------
__global__ void __launch_bounds__(256) final_kernel(const float* __restrict__ x,
                                                    const float* __restrict__ bg,
                                                    float* __restrict__ y) {
    __shared__ float hs[64][D];    // 32KB
    __shared__ float Ws[16][D];    // 8KB
    __shared__ float bsh[D];
    const int n0 = blockIdx.x * 64;
    const int tid = threadIdx.x;

    for (int it = tid; it < 64 * 32; it += 256) {
        int r = it >> 5, c4 = it & 31;
        size_t off = (size_t)(n0 + r) * D + c4 * 4;
        float4 a = *(const float4*)(x + off);
#pragma unroll
        for (int hh = 0; hh < H; hh++) {
            float4 b = *(const float4*)(g_o + (size_t)hh * NT * D + off);
            a.x += b.x; a.y += b.y; a.z += b.z; a.w += b.w;
        }
        *(float4*)&hs[r][c4 * 4] = a;
    }
    if (tid < D) bsh[tid] = bg[tid];

    const int ty = tid >> 4, tx = tid & 15;
    float acc[4][8];
#pragma unroll
    for (int i = 0; i < 4; i++)
#pragma unroll
        for (int j = 0; j < 8; j++) acc[i][j] = 0.f;

    for (int fc = 0; fc < 8; fc++) {
        __syncthreads();
        for (int it = tid; it < 16 * 32; it += 256) {
            int r = it >> 5, c4 = it & 31;
            *(float4*)&Ws[r][c4 * 4] =
                *(const float4*)(g_wgT + (size_t)(fc * 16 + r) * D + c4 * 4);
        }
        __syncthreads();
#pragma unroll
        for (int f = 0; f < 16; f++) {
            float a[4];
#pragma unroll
            for (int ii = 0; ii < 4; ii++) a[ii] = hs[ty * 4 + ii][fc * 16 + f];
            float4 b0 = *(float4*)&Ws[f][tx * 8];
            float4 b1 = *(float4*)&Ws[f][tx * 8 + 4];
            float b[8] = {b0.x, b0.y, b0.z, b0.w, b1.x, b1.y, b1.z, b1.w};
#pragma unroll
            for (int ii = 0; ii < 4; ii++)
#pragma unroll
                for (int jj = 0; jj < 8; jj++)
                    acc[ii][jj] = fmaf(a[ii], b[jj], acc[ii][jj]);
        }
    }

#pragma unroll
    for (int ii = 0; ii < 4; ii++) {
        int n = n0 + ty * 4 + ii;
#pragma unroll
        for (int jj = 0; jj < 8; jj += 4) {
            int d = tx * 8 + jj;
            float4 xv = *(const float4*)(x + (size_t)n * D + d);
            float4 r;
            r.x = xv.x + fmaxf(acc[ii][jj + 0] + bsh[d + 0], 0.f);
            r.y = xv.y + fmaxf(acc[ii][jj + 1] + bsh[d + 1], 0.f);
            r.z = xv.z + fmaxf(acc[ii][jj + 2] + bsh[d + 2], 0.f);
            r.w = xv.w + fmaxf(acc[ii][jj + 3] + bsh[d + 3], 0.f);
            *(float4*)(y + (size_t)n * D + d) = r;
        }
    }
}

// ---------------- launch ----------------------------------------------------
extern "C" void kernel_launch(void* const* d_in, const int* in_sizes, int n_in,
                              void* d_out, int out_size) {
    const float* x  = (const float*)d_in[0];
    const float* Wk = (const float*)d_in[1];
    const float* Wq = (const float*)d_in[2];
    const float* Wv = (const float*)d_in[3];
    const float* Wm = (const float*)d_in[4];
    const float* Wg = (const float*)d_in[5];
    const float* bg = (const float*)d_in[6];
    float* y = (float*)d_out;

    cudaFuncSetAttribute(attn_kernel, cudaFuncAttributeMaxDynamicSharedMemorySize,
                         ATTN_SMEM_BYTES);

    qkv_kernel<<<dim3(NT / 64, H, 3), 256>>>(x, Wk, Wq, Wv);
    attn_kernel<<<dim3(NT / 64, H), 256, ATTN_SMEM_BYTES>>>(Wm);
    wgT_kernel<<<1, 256>>>(Wg);
    final_kernel<<<NT / 64, 256>>>(x, bg, y);
}

// round 3
// speedup vs baseline: 1.0012x; 1.0006x over previous
#include <cuda_runtime.h>
#include <cuda_bf16.h>

#define NT 4096
#define D  128
#define H  8

// ---------------- scratch (device globals; no allocs allowed) ----------------
__device__ float g_q[H * NT * D];
__device__ float g_k[H * NT * D];
__device__ float g_v[H * NT * D];
__device__ float g_o[H * NT * D];
__device__ float g_wgT[D * D];

// ---------------- kernel 1: q/k/v projections -------------------------------
// grid (NT/64, H, 3), block 256.  out[64x128] = x[64x128] @ W[128x128]
__global__ void __launch_bounds__(256) qkv_kernel(const float* __restrict__ x,
                                                  const float* __restrict__ Wk,
                                                  const float* __restrict__ Wq,
                                                  const float* __restrict__ Wv) {
    __shared__ float xs[64][D];    // 32KB
    __shared__ float Ws[16][D];    // 8KB
    const int tile  = blockIdx.x;
    const int h     = blockIdx.y;
    const int which = blockIdx.z;  // 0=q,1=k,2=v
    const float* W = (which == 0 ? Wq : which == 1 ? Wk : Wv) + (size_t)h * D * D;
    float* out = (which == 0 ? g_q : which == 1 ? g_k : g_v)
                 + (size_t)h * NT * D + (size_t)tile * 64 * D;
    const int tid = threadIdx.x;

    for (int it = tid; it < 64 * 32; it += 256) {
        int r = it >> 5, c4 = it & 31;
        *(float4*)&xs[r][c4 * 4] =
            *(const float4*)(x + (size_t)(tile * 64 + r) * D + c4 * 4);
    }
    const int ty = tid >> 4, tx = tid & 15;
    float acc[4][8];
#pragma unroll
    for (int i = 0; i < 4; i++)
#pragma unroll
        for (int j = 0; j < 8; j++) acc[i][j] = 0.f;

    for (int fc = 0; fc < 8; fc++) {
        __syncthreads();
        for (int it = tid; it < 16 * 32; it += 256) {
            int r = it >> 5, c4 = it & 31;
            *(float4*)&Ws[r][c4 * 4] =
                *(const float4*)(W + (size_t)(fc * 16 + r) * D + c4 * 4);
        }
        __syncthreads();
#pragma unroll
        for (int f = 0; f < 16; f++) {
            float a[4];
#pragma unroll
            for (int ii = 0; ii < 4; ii++) a[ii] = xs[ty * 4 + ii][fc * 16 + f];
            float4 b0 = *(float4*)&Ws[f][tx * 8];
            float4 b1 = *(float4*)&Ws[f][tx * 8 + 4];
            float b[8] = {b0.x, b0.y, b0.z, b0.w, b1.x, b1.y, b1.z, b1.w};
#pragma unroll
            for (int ii = 0; ii < 4; ii++)
#pragma unroll
                for (int jj = 0; jj < 8; jj++)
                    acc[ii][jj] = fmaf(a[ii], b[jj], acc[ii][jj]);
        }
    }
#pragma unroll
    for (int ii = 0; ii < 4; ii++) {
        float4 s0 = make_float4(acc[ii][0], acc[ii][1], acc[ii][2], acc[ii][3]);
        float4 s1 = make_float4(acc[ii][4], acc[ii][5], acc[ii][6], acc[ii][7]);
        *(float4*)(out + (size_t)(ty * 4 + ii) * D + tx * 8)     = s0;
        *(float4*)(out + (size_t)(ty * 4 + ii) * D + tx * 8 + 4) = s1;
    }
}

// ---------------- kernel 2: flash attention (fp32) --------------------------
// grid (NT/64, H), block 256, dynamic smem.
// Layout (floats): QsT[128][68] | KsT[128][68] | Vs[64][128] | PsT[64][68]
#define QKT_LD 68
#define ATTN_SMEM_FLOATS (128 * QKT_LD + 128 * QKT_LD + 64 * 128 + 64 * QKT_LD)
#define ATTN_SMEM_BYTES  (ATTN_SMEM_FLOATS * 4)

__global__ void __launch_bounds__(256) attn_kernel(const float* __restrict__ W_m) {
    extern __shared__ float sm[];
    float* QsT = sm;                          // [128][68]  QsT[d][i]
    float* KsT = QsT + 128 * QKT_LD;          // [128][68]  KsT[d][j]
    float* Vs  = KsT + 128 * QKT_LD;          // [64][128]  Vs[j][d]
    float* PsT = Vs + 64 * 128;               // [64][68]   PsT[j][i]

    const int h  = blockIdx.y;
    const int q0 = blockIdx.x * 64;
    const float* qg = g_q + (size_t)h * NT * D;
    const float* kg = g_k + (size_t)h * NT * D;
    const float* vg = g_v + (size_t)h * NT * D;

    const int tid = threadIdx.x;
    const int ty = tid >> 4, tx = tid & 15;   // i0 = 4*ty, j0 = 4*tx, d0 = 8*tx

    // load Q transposed: QsT[d][i] = q[q0+i][d]   (conflict-free scalar STS)
    for (int it = tid; it < 64 * 32; it += 256) {
        int i = it & 63, c4 = it >> 6;
        float4 v = *(const float4*)(qg + (size_t)(q0 + i) * D + c4 * 4);
        QsT[(c4 * 4 + 0) * QKT_LD + i] = v.x;
        QsT[(c4 * 4 + 1) * QKT_LD + i] = v.y;
        QsT[(c4 * 4 + 2) * QKT_LD + i] = v.z;
        QsT[(c4 * 4 + 3) * QKT_LD + i] = v.w;
    }

    float o[4][8];
#pragma unroll
    for (int i = 0; i < 4; i++)
#pragma unroll
        for (int j = 0; j < 8; j++) o[i][j] = 0.f;
    float m[4] = {-1e30f, -1e30f, -1e30f, -1e30f};
    float l[4] = {0.f, 0.f, 0.f, 0.f};

    for (int kb = 0; kb < NT / 64; kb++) {
        const int k0 = kb * 64;
        __syncthreads();   // prior PV reads of KsT/Vs/PsT done (also covers Q load, kb=0)
        // K transposed
        for (int it = tid; it < 64 * 32; it += 256) {
            int j = it & 63, c4 = it >> 6;
            float4 v = *(const float4*)(kg + (size_t)(k0 + j) * D + c4 * 4);
            KsT[(c4 * 4 + 0) * QKT_LD + j] = v.x;
            KsT[(c4 * 4 + 1) * QKT_LD + j] = v.y;
            KsT[(c4 * 4 + 2) * QKT_LD + j] = v.z;
            KsT[(c4 * 4 + 3) * QKT_LD + j] = v.w;
        }
        // V row-major (coalesced)
        for (int it = tid; it < 64 * 32; it += 256) {
            int j = it >> 5, c4 = it & 31;
            *(float4*)&Vs[j * 128 + c4 * 4] =
                *(const float4*)(vg + (size_t)(k0 + j) * D + c4 * 4);
        }
        __syncthreads();

        // ---- S = Q Kᵀ  (4x4 per thread) ----
        float s[4][4];
#pragma unroll
        for (int i = 0; i < 4; i++)
#pragma unroll
            for (int j = 0; j < 4; j++) s[i][j] = 0.f;
#pragma unroll 8
        for (int d = 0; d < D; d++) {
            float4 a = *(float4*)&QsT[d * QKT_LD + 4 * ty];
            float4 b = *(float4*)&KsT[d * QKT_LD + 4 * tx];
            float av[4] = {a.x, a.y, a.z, a.w};
            float bv[4] = {b.x, b.y, b.z, b.w};
#pragma unroll
            for (int i = 0; i < 4; i++)
#pragma unroll
                for (int j = 0; j < 4; j++)
                    s[i][j] = fmaf(av[i], bv[j], s[i][j]);
        }

        // ---- online softmax (rows i owned by the 16-lane tx group) ----
        float corr[4];
#pragma unroll
        for (int ii = 0; ii < 4; ii++) {
            float mx = fmaxf(fmaxf(s[ii][0], s[ii][1]), fmaxf(s[ii][2], s[ii][3]));
#pragma unroll
            for (int off = 8; off >= 1; off >>= 1)
                mx = fmaxf(mx, __shfl_xor_sync(0xffffffffu, mx, off, 16));
            float mnew = fmaxf(m[ii], mx);
            corr[ii] = __expf(m[ii] - mnew);
            m[ii] = mnew;
            float ps = 0.f;
#pragma unroll
            for (int jj = 0; jj < 4; jj++) {
                s[ii][jj] = __expf(s[ii][jj] - mnew);
                ps += s[ii][jj];
            }
#pragma unroll
            for (int off = 8; off >= 1; off >>= 1)
                ps += __shfl_xor_sync(0xffffffffu, ps, off, 16);
            l[ii] = l[ii] * corr[ii] + ps;
        }
        // write P transposed: PsT[j][i]
#pragma unroll
        for (int jj = 0; jj < 4; jj++) {
            float4 pv = make_float4(s[0][jj], s[1][jj], s[2][jj], s[3][jj]);
            *(float4*)&PsT[(4 * tx + jj) * QKT_LD + 4 * ty] = pv;
        }
        // rescale O
#pragma unroll
        for (int ii = 0; ii < 4; ii++)
#pragma unroll
            for (int dd = 0; dd < 8; dd++) o[ii][dd] *= corr[ii];
        __syncthreads();

        // ---- O += P V ----
#pragma unroll 4
        for (int j = 0; j < 64; j++) {
            float4 pp = *(float4*)&PsT[j * QKT_LD + 4 * ty];
            float4 v0 = *(float4*)&Vs[j * 128 + 8 * tx];
            float4 v1 = *(float4*)&Vs[j * 128 + 8 * tx + 4];
            float pv[4] = {pp.x, pp.y, pp.z, pp.w};
            float vv[8] = {v0.x, v0.y, v0.z, v0.w, v1.x, v1.y, v1.z, v1.w};
#pragma unroll
            for (int ii = 0; ii < 4; ii++)
#pragma unroll
                for (int dd = 0; dd < 8; dd++)
                    o[ii][dd] = fmaf(pv[ii], vv[dd], o[ii][dd]);
        }
    }

    // epilogue: O/l * W_m[h] -> g_o
    const float wm = W_m[h];
    float* og = g_o + (size_t)h * NT * D;
#pragma unroll
    for (int ii = 0; ii < 4; ii++) {
        float inv = wm / l[ii];
        float4 s0 = make_float4(o[ii][0] * inv, o[ii][1] * inv,
                                o[ii][2] * inv, o[ii][3] * inv);
        float4 s1 = make_float4(o[ii][4] * inv, o[ii][5] * inv,
                                o[ii][6] * inv, o[ii][7] * inv);
        size_t row = (size_t)(q0 + 4 * ty + ii) * D;
        *(float4*)(og + row + 8 * tx)     = s0;
        *(float4*)(og + row + 8 * tx + 4) = s1;
    }
}

// ---------------- kernel 2.5: transpose Wg ----------------------------------
__global__ void wgT_kernel(const float* __restrict__ Wg) {
    for (int it = threadIdx.x; it < D * D; it += blockDim.x) {
        int d = it >> 7, f = it & 127;
        g_wgT[f * D + d] = Wg[d * D + f];
    }
}

// ---------------- kernel 3: y = x + relu((x + sum_h o) @ WgT + bg) ----------
__global__ void __launch_bounds__(256) final_kernel(const float* __restrict__ x,
                                                    const float* __restrict__ bg,
                                                    float* __restrict__ y) {
    __shared__ float hs[64][D];    // 32KB
    __shared__ float Ws[16][D];    // 8KB
    __shared__ float bsh[D];
    const int n0 = blockIdx.x * 64;
    const int tid = threadIdx.x;

    for (int it = tid; it < 64 * 32; it += 256) {
        int r = it >> 5, c4 = it & 31;
        size_t off = (size_t)(n0 + r) * D + c4 * 4;
        float4 a = *(const float4*)(x + off);
#pragma unroll
        for (int hh = 0; hh < H; hh++) {
            float4 b = *(const float4*)(g_o + (size_t)hh * NT * D + off);
            a.x += b.x; a.y += b.y; a.z += b.z; a.w += b.w;
        }
        *(float4*)&hs[r][c4 * 4] = a;
    }
    if (tid < D) bsh[tid] = bg[tid];

    const int ty = tid >> 4, tx = tid & 15;
    float acc[4][8];
#pragma unroll
    for (int i = 0; i < 4; i++)
#pragma unroll
        for (int j = 0; j < 8; j++) acc[i][j] = 0.f;

    for (int fc = 0; fc < 8; fc++) {
        __syncthreads();
        for (int it = tid; it < 16 * 32; it += 256) {
            int r = it >> 5, c4 = it & 31;
            *(float4*)&Ws[r][c4 * 4] =
                *(const float4*)(g_wgT + (size_t)(fc * 16 + r) * D + c4 * 4);
        }
        __syncthreads();
#pragma unroll
        for (int f = 0; f < 16; f++) {
            float a[4];
#pragma unroll
            for (int ii = 0; ii < 4; ii++) a[ii] = hs[ty * 4 + ii][fc * 16 + f];
            float4 b0 = *(float4*)&Ws[f][tx * 8];
            float4 b1 = *(float4*)&Ws[f][tx * 8 + 4];
            float b[8] = {b0.x, b0.y, b0.z, b0.w, b1.x, b1.y, b1.z, b1.w};
#pragma unroll
            for (int ii = 0; ii < 4; ii++)
#pragma unroll
                for (int jj = 0; jj < 8; jj++)
                    acc[ii][jj] = fmaf(a[ii], b[jj], acc[ii][jj]);
        }
    }

#pragma unroll
    for (int ii = 0; ii < 4; ii++) {
        int n = n0 + ty * 4 + ii;
#pragma unroll
        for (int jj = 0; jj < 8; jj += 4) {
            int d = tx * 8 + jj;
            float4 xv = *(const float4*)(x + (size_t)n * D + d);
            float4 r;
            r.x = xv.x + fmaxf(acc[ii][jj + 0] + bsh[d + 0], 0.f);
            r.y = xv.y + fmaxf(acc[ii][jj + 1] + bsh[d + 1], 0.f);
            r.z = xv.z + fmaxf(acc[ii][jj + 2] + bsh[d + 2], 0.f);
            r.w = xv.w + fmaxf(acc[ii][jj + 3] + bsh[d + 3], 0.f);
            *(float4*)(y + (size_t)n * D + d) = r;
        }
    }
}

// ---------------- launch ----------------------------------------------------
extern "C" void kernel_launch(void* const* d_in, const int* in_sizes, int n_in,
                              void* d_out, int out_size) {
    const float* x  = (const float*)d_in[0];
    const float* Wk = (const float*)d_in[1];
    const float* Wq = (const float*)d_in[2];
    const float* Wv = (const float*)d_in[3];
    const float* Wm = (const float*)d_in[4];
    const float* Wg = (const float*)d_in[5];
    const float* bg = (const float*)d_in[6];
    float* y = (float*)d_out;

    cudaFuncSetAttribute(attn_kernel, cudaFuncAttributeMaxDynamicSharedMemorySize,
                         ATTN_SMEM_BYTES);

    qkv_kernel<<<dim3(NT / 64, H, 3), 256>>>(x, Wk, Wq, Wv);
    attn_kernel<<<dim3(NT / 64, H), 256, ATTN_SMEM_BYTES>>>(Wm);
    wgT_kernel<<<1, 256>>>(Wg);
    final_kernel<<<NT / 64, 256>>>(x, bg, y);
}

// round 5
// speedup vs baseline: 4.2837x; 4.2784x over previous
#include <cuda_runtime.h>
#include <cuda_fp16.h>
#include <cstdint>

#define NT 4096
#define D  128
#define H  8
#define BN 64
#define NB (NT / BN)

// ---------------- scratch globals ---------------------------------------------
__device__ __align__(16) __half g_qh[H * NT * D];
__device__ __align__(16) __half g_ql[H * NT * D];
__device__ __align__(16) __half g_kh[H * NT * D];
__device__ __align__(16) __half g_kl[H * NT * D];
__device__ __align__(16) __half g_vh[H * D * NT];  // transposed [h][d][n]
__device__ __align__(16) __half g_vl[H * D * NT];
__device__ __align__(16) float  g_o[H * NT * D];
__device__ float g_wgT[D * D];

// ---------------- helpers -------------------------------------------------------
__device__ __forceinline__ float ex2f(float x) {
    float y; asm("ex2.approx.ftz.f32 %0,%1;" : "=f"(y) : "f"(x)); return y;
}
#define CP16(d, s) asm volatile("cp.async.cg.shared.global [%0],[%1],16;" :: "r"(d), "l"(s) : "memory")
#define CPC()  asm volatile("cp.async.commit_group;" ::: "memory")
#define CPW1() asm volatile("cp.async.wait_group 1;" ::: "memory")

__device__ __forceinline__ uint32_t su32(const void* p) {
    return (uint32_t)__cvta_generic_to_shared(p);
}

// mma.m16n8k16 fp16 in, fp32 accumulate (in-place)
__device__ __forceinline__ void mma(float* c, const uint32_t* a, uint32_t b0, uint32_t b1) {
    asm volatile(
        "mma.sync.aligned.m16n8k16.row.col.f32.f16.f16.f32 "
        "{%0,%1,%2,%3},{%4,%5,%6,%7},{%8,%9},{%0,%1,%2,%3};"
        : "+f"(c[0]), "+f"(c[1]), "+f"(c[2]), "+f"(c[3])
        : "r"(a[0]), "r"(a[1]), "r"(a[2]), "r"(a[3]), "r"(b0), "r"(b1));
}

__device__ __forceinline__ void pack2(float a, float b, uint32_t& hi, uint32_t& lo) {
    __half2 h = __floats2half2_rn(a, b);
    float2 f = __half22float2(h);
    __half2 r = __floats2half2_rn(a - f.x, b - f.y);
    hi = *(uint32_t*)&h; lo = *(uint32_t*)&r;
}

// smem layout per stage: Kh[64][136] Kl[64][136] VhT[128][72] VlT[128][72] (halves)
#define KROW 136
#define VROW 72
#define ST_K (64 * KROW * 2)               // 17408 B
#define ST_V (128 * VROW * 2)              // 18432 B
#define STAGE (2 * ST_K + 2 * ST_V)        // 71680 B
#define ASMEM (2 * STAGE)                  // 143360 B

__device__ __forceinline__ void load_stage(uint32_t sb, int h, int kb, int tid) {
    size_t kof = (size_t)h * NT * D + (size_t)kb * BN * D;
    size_t vof = (size_t)h * D * NT + (size_t)kb * BN;
    for (int c = tid; c < 1024; c += 256) {          // K: 64 rows x 16 chunks
        int r = c >> 4, k = c & 15;
        uint32_t so = (uint32_t)(r * (KROW * 2) + k * 16);
        CP16(sb + so,        g_kh + kof + (size_t)r * D + k * 8);
        CP16(sb + ST_K + so, g_kl + kof + (size_t)r * D + k * 8);
    }
    for (int c = tid; c < 1024; c += 256) {          // V: 128 rows x 8 chunks
        int r = c >> 3, k = c & 7;
        uint32_t so = (uint32_t)(r * (VROW * 2) + k * 16);
        CP16(sb + 2 * ST_K + so,        g_vh + vof + (size_t)r * NT + k * 8);
        CP16(sb + 2 * ST_K + ST_V + so, g_vl + vof + (size_t)r * NT + k * 8);
    }
}

// ---------------- attention: grid (32, 8), 256 threads -------------------------
__global__ void __launch_bounds__(256) attn_kernel(const float* __restrict__ W_m) {
    extern __shared__ char sm[];
    const int tid = threadIdx.x, w = tid >> 5, l = tid & 31;
    const int h = blockIdx.y, q0 = blockIdx.x * 128;
    const int lq = l >> 2, lr = l & 3;

    // Q fragments (hi/lo), 8 ksteps x 4 regs each — direct from gmem
    uint32_t qa[2][8][4];
    {
        const __half* q0p = g_qh + ((size_t)h * NT + q0 + w * 16) * D;
        const __half* q1p = g_ql + ((size_t)h * NT + q0 + w * 16) * D;
#pragma unroll
        for (int s = 0; s < 2; s++) {
            const __half* qs = s ? q1p : q0p;
#pragma unroll
            for (int j = 0; j < 8; j++) {
                const __half* base = qs + (size_t)lq * D + j * 16 + lr * 2;
                qa[s][j][0] = *(const uint32_t*)(base);
                qa[s][j][1] = *(const uint32_t*)(base + 8 * D);
                qa[s][j][2] = *(const uint32_t*)(base + 8);
                qa[s][j][3] = *(const uint32_t*)(base + 8 * D + 8);
            }
        }
    }

    const uint32_t sb = su32(sm);
    load_stage(sb, h, 0, tid); CPC();

    float o[16][4];
#pragma unroll
    for (int t = 0; t < 16; t++) { o[t][0] = o[t][1] = o[t][2] = o[t][3] = 0.f; }
    float m0 = -1e30f, m1 = -1e30f, l0 = 0.f, l1 = 0.f;
    const float L2E = 1.4426950408889634f;

    for (int kb = 0; kb < NB; kb++) {
        __syncthreads();
        if (kb + 1 < NB) load_stage(sb + (uint32_t)(((kb + 1) & 1) * STAGE), h, kb + 1, tid);
        CPC(); CPW1();
        __syncthreads();

        const char* stg = sm + (kb & 1) * STAGE;
        const uint32_t* Kh32 = (const uint32_t*)(stg);
        const uint32_t* Kl32 = (const uint32_t*)(stg + ST_K);
        const uint32_t* Vh32 = (const uint32_t*)(stg + 2 * ST_K);
        const uint32_t* Vl32 = (const uint32_t*)(stg + 2 * ST_K + ST_V);

        // ---- S = QhKh + QlKh + QhKl  (16x64 per warp) ----
        float s[8][4];
#pragma unroll
        for (int t = 0; t < 8; t++) { s[t][0] = s[t][1] = s[t][2] = s[t][3] = 0.f; }
#pragma unroll
        for (int t = 0; t < 8; t++) {
            int krow = 8 * t + lq;     // key row in [64][136] tile
#pragma unroll
            for (int j = 0; j < 8; j++) {
                int bi = krow * (KROW / 2) + j * 8 + lr;
                uint32_t b0 = Kh32[bi], b1 = Kh32[bi + 4];
                uint32_t c0 = Kl32[bi], c1 = Kl32[bi + 4];
                mma(s[t], qa[0][j], b0, b1);
                mma(s[t], qa[1][j], b0, b1);
                mma(s[t], qa[0][j], c0, c1);
            }
        }

        // ---- online softmax (rows lq, lq+8; quad-reduced) ----
        float rx0 = -1e30f, rx1 = -1e30f;
#pragma unroll
        for (int t = 0; t < 8; t++) {
            rx0 = fmaxf(rx0, fmaxf(s[t][0], s[t][1]));
            rx1 = fmaxf(rx1, fmaxf(s[t][2], s[t][3]));
        }
        rx0 = fmaxf(rx0, __shfl_xor_sync(~0u, rx0, 1));
        rx0 = fmaxf(rx0, __shfl_xor_sync(~0u, rx0, 2));
        rx1 = fmaxf(rx1, __shfl_xor_sync(~0u, rx1, 1));
        rx1 = fmaxf(rx1, __shfl_xor_sync(~0u, rx1, 2));
        float mn0 = fmaxf(m0, rx0), mn1 = fmaxf(m1, rx1);
        float sc0 = ex2f((m0 - mn0) * L2E), sc1 = ex2f((m1 - mn1) * L2E);
        m0 = mn0; m1 = mn1;
        float rs0 = 0.f, rs1 = 0.f;
#pragma unroll
        for (int t = 0; t < 8; t++) {
            s[t][0] = ex2f((s[t][0] - mn0) * L2E);
            s[t][1] = ex2f((s[t][1] - mn0) * L2E);
            s[t][2] = ex2f((s[t][2] - mn1) * L2E);
            s[t][3] = ex2f((s[t][3] - mn1) * L2E);
            rs0 += s[t][0] + s[t][1];
            rs1 += s[t][2] + s[t][3];
        }
        rs0 += __shfl_xor_sync(~0u, rs0, 1); rs0 += __shfl_xor_sync(~0u, rs0, 2);
        rs1 += __shfl_xor_sync(~0u, rs1, 1); rs1 += __shfl_xor_sync(~0u, rs1, 2);
        l0 = l0 * sc0 + rs0; l1 = l1 * sc1 + rs1;
#pragma unroll
        for (int t = 0; t < 16; t++) {
            o[t][0] *= sc0; o[t][1] *= sc0; o[t][2] *= sc1; o[t][3] *= sc1;
        }

        // ---- pack P (hi/lo) straight from the S accumulator layout ----
        uint32_t ph[4][4], pl[4][4];
#pragma unroll
        for (int j = 0; j < 4; j++) {
            pack2(s[2 * j][0],     s[2 * j][1],     ph[j][0], pl[j][0]);
            pack2(s[2 * j][2],     s[2 * j][3],     ph[j][1], pl[j][1]);
            pack2(s[2 * j + 1][0], s[2 * j + 1][1], ph[j][2], pl[j][2]);
            pack2(s[2 * j + 1][2], s[2 * j + 1][3], ph[j][3], pl[j][3]);
        }

        // ---- O += PhVh + PlVh + PhVl ----
#pragma unroll
        for (int t = 0; t < 16; t++) {
            int vr = 8 * t + lq;       // dim row in [128][72] tile
#pragma unroll
            for (int j = 0; j < 4; j++) {
                int bi = vr * (VROW / 2) + j * 8 + lr;
                uint32_t b0 = Vh32[bi], b1 = Vh32[bi + 4];
                uint32_t d0 = Vl32[bi], d1 = Vl32[bi + 4];
                mma(o[t], ph[j], b0, b1);
                mma(o[t], pl[j], b0, b1);
                mma(o[t], ph[j], d0, d1);
            }
        }
    }

    // ---- epilogue: scale by W_m[h]/l, store ----
    float wm = W_m[h];
    float i0 = wm / l0, i1 = wm / l1;
    float* og = g_o + ((size_t)h * NT + q0 + w * 16) * D;
#pragma unroll
    for (int t = 0; t < 16; t++) {
        int col = 8 * t + lr * 2;
        *(float2*)(og + (size_t)lq * D + col)       = make_float2(o[t][0] * i0, o[t][1] * i0);
        *(float2*)(og + (size_t)(lq + 8) * D + col) = make_float2(o[t][2] * i1, o[t][3] * i1);
    }
}

// ---------------- qkv projections + fp16 splits --------------------------------
__global__ void __launch_bounds__(256) qkv_kernel(const float* __restrict__ x,
                                                  const float* __restrict__ Wk,
                                                  const float* __restrict__ Wq,
                                                  const float* __restrict__ Wv) {
    __shared__ float xs[64][D];
    __shared__ float Ws[16][D];
    const int tile = blockIdx.x, h = blockIdx.y, which = blockIdx.z;
    const float* W = (which == 0 ? Wq : which == 1 ? Wk : Wv) + (size_t)h * D * D;
    const int tid = threadIdx.x;

    for (int it = tid; it < 64 * 32; it += 256) {
        int r = it >> 5, c4 = it & 31;
        *(float4*)&xs[r][c4 * 4] = *(const float4*)(x + (size_t)(tile * 64 + r) * D + c4 * 4);
    }
    const int ty = tid >> 4, tx = tid & 15;
    float acc[4][8];
#pragma unroll
    for (int i = 0; i < 4; i++)
#pragma unroll
        for (int j = 0; j < 8; j++) acc[i][j] = 0.f;

    for (int fc = 0; fc < 8; fc++) {
        __syncthreads();
        for (int it = tid; it < 16 * 32; it += 256) {
            int r = it >> 5, c4 = it & 31;
            *(float4*)&Ws[r][c4 * 4] = *(const float4*)(W + (size_t)(fc * 16 + r) * D + c4 * 4);
        }
        __syncthreads();
#pragma unroll
        for (int f = 0; f < 16; f++) {
            float a[4];
#pragma unroll
            for (int ii = 0; ii < 4; ii++) a[ii] = xs[ty * 4 + ii][fc * 16 + f];
            float4 b0 = *(float4*)&Ws[f][tx * 8];
            float4 b1 = *(float4*)&Ws[f][tx * 8 + 4];
            float b[8] = {b0.x, b0.y, b0.z, b0.w, b1.x, b1.y, b1.z, b1.w};
#pragma unroll
            for (int ii = 0; ii < 4; ii++)
#pragma unroll
                for (int jj = 0; jj < 8; jj++)
                    acc[ii][jj] = fmaf(a[ii], b[jj], acc[ii][jj]);
        }
    }

    if (which == 2) {  // V: fp16 split, transposed [h][d][n]
#pragma unroll
        for (int ii = 0; ii < 4; ii++) {
            int n = tile * 64 + ty * 4 + ii;
#pragma unroll
            for (int jj = 0; jj < 8; jj++) {
                int d = tx * 8 + jj;
                float v = acc[ii][jj];
                __half hi = __float2half_rn(v);
                __half lo = __float2half_rn(v - __half2float(hi));
                size_t idx = (size_t)h * D * NT + (size_t)d * NT + n;
                g_vh[idx] = hi; g_vl[idx] = lo;
            }
        }
    } else {           // Q/K: fp16 split, row-major
        __half* oh = (which == 0 ? g_qh : g_kh) + ((size_t)h * NT + tile * 64) * D;
        __half* ol = (which == 0 ? g_ql : g_kl) + ((size_t)h * NT + tile * 64) * D;
#pragma unroll
        for (int ii = 0; ii < 4; ii++) {
            __align__(16) __half hb[8], lb[8];
#pragma unroll
            for (int jj = 0; jj < 8; jj++) {
                float a = acc[ii][jj];
                __half hh = __float2half_rn(a);
                hb[jj] = hh;
                lb[jj] = __float2half_rn(a - __half2float(hh));
            }
            size_t off = (size_t)(ty * 4 + ii) * D + tx * 8;
            *(uint4*)(oh + off) = *(uint4*)hb;
            *(uint4*)(ol + off) = *(uint4*)lb;
        }
    }
}

// ---------------- Wg transpose + final MLP --------------------------------------
__global__ void wgT_kernel(const float* __restrict__ Wg) {
    for (int it = threadIdx.x; it < D * D; it += blockDim.x) {
        int d = it >> 7, f = it & 127;
        g_wgT[f * D + d] = Wg[d * D + f];
    }
}

__global__ void __launch_bounds__(256) final_kernel(const float* __restrict__ x,
                                                    const float* __restrict__ bg,
                                                    float* __restrict__ y) {
    __shared__ float hs[64][D];
    __shared__ float Ws[16][D];
    __shared__ float bsh[D];
    const int n0 = blockIdx.x * 64;
    const int tid = threadIdx.x;

    for (int it = tid; it < 64 * 32; it += 256) {
        int r = it >> 5, c4 = it & 31;
        size_t off = (size_t)(n0 + r) * D + c4 * 4;
        float4 a = *(const float4*)(x + off);
#pragma unroll
        for (int hh = 0; hh < H; hh++) {
            float4 b = *(const float4*)(g_o + (size_t)hh * NT * D + off);
            a.x += b.x; a.y += b.y; a.z += b.z; a.w += b.w;
        }
        *(float4*)&hs[r][c4 * 4] = a;
    }
    if (tid < D) bsh[tid] = bg[tid];

    const int ty = tid >> 4, tx = tid & 15;
    float acc[4][8];
#pragma unroll
    for (int i = 0; i < 4; i++)
#pragma unroll
        for (int j = 0; j < 8; j++) acc[i][j] = 0.f;

    for (int fc = 0; fc < 8; fc++) {
        __syncthreads();
        for (int it = tid; it < 16 * 32; it += 256) {
            int r = it >> 5, c4 = it & 31;
            *(float4*)&Ws[r][c4 * 4] = *(const float4*)(g_wgT + (size_t)(fc * 16 + r) * D + c4 * 4);
        }
        __syncthreads();
#pragma unroll
        for (int f = 0; f < 16; f++) {
            float a[4];
#pragma unroll
            for (int ii = 0; ii < 4; ii++) a[ii] = hs[ty * 4 + ii][fc * 16 + f];
            float4 b0 = *(float4*)&Ws[f][tx * 8];
            float4 b1 = *(float4*)&Ws[f][tx * 8 + 4];
            float b[8] = {b0.x, b0.y, b0.z, b0.w, b1.x, b1.y, b1.z, b1.w};
#pragma unroll
            for (int ii = 0; ii < 4; ii++)
#pragma unroll
                for (int jj = 0; jj < 8; jj++)
                    acc[ii][jj] = fmaf(a[ii], b[jj], acc[ii][jj]);
        }
    }

#pragma unroll
    for (int ii = 0; ii < 4; ii++) {
        int n = n0 + ty * 4 + ii;
#pragma unroll
        for (int jj = 0; jj < 8; jj += 4) {
            int d = tx * 8 + jj;
            float4 xv = *(const float4*)(x + (size_t)n * D + d);
            float4 r;
            r.x = xv.x + fmaxf(acc[ii][jj + 0] + bsh[d + 0], 0.f);
            r.y = xv.y + fmaxf(acc[ii][jj + 1] + bsh[d + 1], 0.f);
            r.z = xv.z + fmaxf(acc[ii][jj + 2] + bsh[d + 2], 0.f);
            r.w = xv.w + fmaxf(acc[ii][jj + 3] + bsh[d + 3], 0.f);
            *(float4*)(y + (size_t)n * D + d) = r;
        }
    }
}

// ---------------- launch ---------------------------------------------------------
extern "C" void kernel_launch(void* const* d_in, const int* in_sizes, int n_in,
                              void* d_out, int out_size) {
    const float* x  = (const float*)d_in[0];
    const float* Wk = (const float*)d_in[1];
    const float* Wq = (const float*)d_in[2];
    const float* Wv = (const float*)d_in[3];
    const float* Wm = (const float*)d_in[4];
    const float* Wg = (const float*)d_in[5];
    const float* bg = (const float*)d_in[6];
    float* y = (float*)d_out;

    cudaFuncSetAttribute(attn_kernel, cudaFuncAttributeMaxDynamicSharedMemorySize, ASMEM);

    qkv_kernel<<<dim3(NT / 64, H, 3), 256>>>(x, Wk, Wq, Wv);
    attn_kernel<<<dim3(NT / 128, H), 256, ASMEM>>>(Wm);
    wgT_kernel<<<1, 256>>>(Wg);
    final_kernel<<<NT / 64, 256>>>(x, bg, y);
}

// round 6
// speedup vs baseline: 5.3920x; 1.2587x over previous
#include <cuda_runtime.h>
#include <cuda_fp16.h>
#include <cstdint>

#define NT 4096
#define D  128
#define H  8
#define BN 64
#define NB (NT / BN)

// ---------------- scratch globals ---------------------------------------------
__device__ __align__(16) __half g_qh[H * NT * D];
__device__ __align__(16) __half g_ql[H * NT * D];
__device__ __align__(16) __half g_kh[H * NT * D];
__device__ __align__(16) __half g_kl[H * NT * D];
__device__ __align__(16) __half g_vh[H * D * NT];   // transposed [h][d][n], fp16 only
__device__ __align__(16) float  g_o[H * NT * D];
__device__ float g_wgT[D * D];

__device__ __align__(16) __half g_xh[NT * D];
__device__ __align__(16) __half g_xl[NT * D];
// W^T split: [h][dout][f]
__device__ __align__(16) __half g_wT[3][2][H * D * D];   // [which][hi/lo]

// ---------------- helpers -------------------------------------------------------
__device__ __forceinline__ float ex2f(float x) {
    float y; asm("ex2.approx.ftz.f32 %0,%1;" : "=f"(y) : "f"(x)); return y;
}
#define CP16(d, s) asm volatile("cp.async.cg.shared.global [%0],[%1],16;" :: "r"(d), "l"(s) : "memory")
#define CPC()  asm volatile("cp.async.commit_group;" ::: "memory")
#define CPW0() asm volatile("cp.async.wait_group 0;" ::: "memory")
#define CPW1() asm volatile("cp.async.wait_group 1;" ::: "memory")

__device__ __forceinline__ uint32_t su32(const void* p) {
    return (uint32_t)__cvta_generic_to_shared(p);
}

__device__ __forceinline__ void mma(float* c, const uint32_t* a, uint32_t b0, uint32_t b1) {
    asm volatile(
        "mma.sync.aligned.m16n8k16.row.col.f32.f16.f16.f32 "
        "{%0,%1,%2,%3},{%4,%5,%6,%7},{%8,%9},{%0,%1,%2,%3};"
        : "+f"(c[0]), "+f"(c[1]), "+f"(c[2]), "+f"(c[3])
        : "r"(a[0]), "r"(a[1]), "r"(a[2]), "r"(a[3]), "r"(b0), "r"(b1));
}

__device__ __forceinline__ void pack2(float a, float b, uint32_t& hi, uint32_t& lo) {
    __half2 h = __floats2half2_rn(a, b);
    float2 f = __half22float2(h);
    __half2 r = __floats2half2_rn(a - f.x, b - f.y);
    hi = *(uint32_t*)&h; lo = *(uint32_t*)&r;
}

// ================== attention smem: Kh[64][136] Kl[64][136] Vh[128][72] =========
#define KROW 136
#define VROW 72
#define ST_K (64 * KROW * 2)               // 17408 B
#define ST_V (128 * VROW * 2)              // 18432 B
#define STAGE (2 * ST_K + ST_V)            // 53248 B
#define ASMEM (2 * STAGE)                  // 106496 B

__device__ __forceinline__ void load_stage(uint32_t sb, int h, int kb, int tid) {
    size_t kof = (size_t)h * NT * D + (size_t)kb * BN * D;
    size_t vof = (size_t)h * D * NT + (size_t)kb * BN;
    for (int c = tid; c < 1024; c += 256) {          // K: 64 rows x 16 chunks
        int r = c >> 4, k = c & 15;
        uint32_t so = (uint32_t)(r * (KROW * 2) + k * 16);
        CP16(sb + so,        g_kh + kof + (size_t)r * D + k * 8);
        CP16(sb + ST_K + so, g_kl + kof + (size_t)r * D + k * 8);
    }
    for (int c = tid; c < 1024; c += 256) {          // Vh: 128 rows x 8 chunks
        int r = c >> 3, k = c & 7;
        CP16(sb + 2 * ST_K + (uint32_t)(r * (VROW * 2) + k * 16),
             g_vh + vof + (size_t)r * NT + k * 8);
    }
}

// ---------------- attention: grid (32, 8), 256 threads -------------------------
__global__ void __launch_bounds__(256) attn_kernel(const float* __restrict__ W_m) {
    extern __shared__ char sm[];
    const int tid = threadIdx.x, w = tid >> 5, l = tid & 31;
    const int h = blockIdx.y, q0 = blockIdx.x * 128;
    const int lq = l >> 2, lr = l & 3;

    uint32_t qa[2][8][4];
    {
        const __half* q0p = g_qh + ((size_t)h * NT + q0 + w * 16) * D;
        const __half* q1p = g_ql + ((size_t)h * NT + q0 + w * 16) * D;
#pragma unroll
        for (int s = 0; s < 2; s++) {
            const __half* qs = s ? q1p : q0p;
#pragma unroll
            for (int j = 0; j < 8; j++) {
                const __half* base = qs + (size_t)lq * D + j * 16 + lr * 2;
                qa[s][j][0] = *(const uint32_t*)(base);
                qa[s][j][1] = *(const uint32_t*)(base + 8 * D);
                qa[s][j][2] = *(const uint32_t*)(base + 8);
                qa[s][j][3] = *(const uint32_t*)(base + 8 * D + 8);
            }
        }
    }

    const uint32_t sb = su32(sm);
    load_stage(sb, h, 0, tid); CPC();

    float o[16][4];
#pragma unroll
    for (int t = 0; t < 16; t++) { o[t][0] = o[t][1] = o[t][2] = o[t][3] = 0.f; }
    float m0 = -1e30f, m1 = -1e30f, l0 = 0.f, l1 = 0.f;
    const float L2E = 1.4426950408889634f;

    for (int kb = 0; kb < NB; kb++) {
        __syncthreads();
        if (kb + 1 < NB) load_stage(sb + (uint32_t)(((kb + 1) & 1) * STAGE), h, kb + 1, tid);
        CPC(); CPW1();
        __syncthreads();

        const char* stg = sm + (kb & 1) * STAGE;
        const uint32_t* Kh32 = (const uint32_t*)(stg);
        const uint32_t* Kl32 = (const uint32_t*)(stg + ST_K);
        const uint32_t* Vh32 = (const uint32_t*)(stg + 2 * ST_K);

        // ---- S = QhKh + QlKh + QhKl ----
        float s[8][4];
#pragma unroll
        for (int t = 0; t < 8; t++) { s[t][0] = s[t][1] = s[t][2] = s[t][3] = 0.f; }
#pragma unroll
        for (int t = 0; t < 8; t++) {
            int krow = 8 * t + lq;
#pragma unroll
            for (int j = 0; j < 8; j++) {
                int bi = krow * (KROW / 2) + j * 8 + lr;
                uint32_t b0 = Kh32[bi], b1 = Kh32[bi + 4];
                uint32_t c0 = Kl32[bi], c1 = Kl32[bi + 4];
                mma(s[t], qa[0][j], b0, b1);
                mma(s[t], qa[1][j], b0, b1);
                mma(s[t], qa[0][j], c0, c1);
            }
        }

        // ---- online softmax ----
        float rx0 = -1e30f, rx1 = -1e30f;
#pragma unroll
        for (int t = 0; t < 8; t++) {
            rx0 = fmaxf(rx0, fmaxf(s[t][0], s[t][1]));
            rx1 = fmaxf(rx1, fmaxf(s[t][2], s[t][3]));
        }
        rx0 = fmaxf(rx0, __shfl_xor_sync(~0u, rx0, 1));
        rx0 = fmaxf(rx0, __shfl_xor_sync(~0u, rx0, 2));
        rx1 = fmaxf(rx1, __shfl_xor_sync(~0u, rx1, 1));
        rx1 = fmaxf(rx1, __shfl_xor_sync(~0u, rx1, 2));
        float mn0 = fmaxf(m0, rx0), mn1 = fmaxf(m1, rx1);
        float sc0 = ex2f((m0 - mn0) * L2E), sc1 = ex2f((m1 - mn1) * L2E);
        m0 = mn0; m1 = mn1;
        float rs0 = 0.f, rs1 = 0.f;
#pragma unroll
        for (int t = 0; t < 8; t++) {
            s[t][0] = ex2f((s[t][0] - mn0) * L2E);
            s[t][1] = ex2f((s[t][1] - mn0) * L2E);
            s[t][2] = ex2f((s[t][2] - mn1) * L2E);
            s[t][3] = ex2f((s[t][3] - mn1) * L2E);
            rs0 += s[t][0] + s[t][1];
            rs1 += s[t][2] + s[t][3];
        }
        rs0 += __shfl_xor_sync(~0u, rs0, 1); rs0 += __shfl_xor_sync(~0u, rs0, 2);
        rs1 += __shfl_xor_sync(~0u, rs1, 1); rs1 += __shfl_xor_sync(~0u, rs1, 2);
        l0 = l0 * sc0 + rs0; l1 = l1 * sc1 + rs1;
#pragma unroll
        for (int t = 0; t < 16; t++) {
            o[t][0] *= sc0; o[t][1] *= sc0; o[t][2] *= sc1; o[t][3] *= sc1;
        }

        uint32_t ph[4][4], pl[4][4];
#pragma unroll
        for (int j = 0; j < 4; j++) {
            pack2(s[2 * j][0],     s[2 * j][1],     ph[j][0], pl[j][0]);
            pack2(s[2 * j][2],     s[2 * j][3],     ph[j][1], pl[j][1]);
            pack2(s[2 * j + 1][0], s[2 * j + 1][1], ph[j][2], pl[j][2]);
            pack2(s[2 * j + 1][2], s[2 * j + 1][3], ph[j][3], pl[j][3]);
        }

        // ---- O += PhVh + PlVh  (2-term; V fp16) ----
#pragma unroll
        for (int t = 0; t < 16; t++) {
            int vr = 8 * t + lq;
#pragma unroll
            for (int j = 0; j < 4; j++) {
                int bi = vr * (VROW / 2) + j * 8 + lr;
                uint32_t b0 = Vh32[bi], b1 = Vh32[bi + 4];
                mma(o[t], ph[j], b0, b1);
                mma(o[t], pl[j], b0, b1);
            }
        }
    }

    float wm = W_m[h];
    float i0 = wm / l0, i1 = wm / l1;
    float* og = g_o + ((size_t)h * NT + q0 + w * 16) * D;
#pragma unroll
    for (int t = 0; t < 16; t++) {
        int col = 8 * t + lr * 2;
        *(float2*)(og + (size_t)lq * D + col)       = make_float2(o[t][0] * i0, o[t][1] * i0);
        *(float2*)(og + (size_t)(lq + 8) * D + col) = make_float2(o[t][2] * i1, o[t][3] * i1);
    }
}

// ================== prep: split x, split+transpose W ============================
__global__ void __launch_bounds__(256) splitx_kernel(const float* __restrict__ x) {
    int base = (blockIdx.x * 256 + threadIdx.x) * 8;
    float4 a = *(const float4*)(x + base);
    float4 b = *(const float4*)(x + base + 4);
    float v[8] = {a.x, a.y, a.z, a.w, b.x, b.y, b.z, b.w};
    __align__(16) __half hb[8], lb[8];
#pragma unroll
    for (int i = 0; i < 8; i++) {
        __half hh = __float2half_rn(v[i]);
        hb[i] = hh;
        lb[i] = __float2half_rn(v[i] - __half2float(hh));
    }
    *(uint4*)(g_xh + base) = *(uint4*)hb;
    *(uint4*)(g_xl + base) = *(uint4*)lb;
}

__global__ void __launch_bounds__(256) splitW_kernel(const float* __restrict__ Wk,
                                                     const float* __restrict__ Wq,
                                                     const float* __restrict__ Wv) {
    const int h = blockIdx.x, which = blockIdx.y;  // 0=q,1=k,2=v
    const float* W = (which == 0 ? Wq : which == 1 ? Wk : Wv) + (size_t)h * D * D;
    __half* oh = g_wT[which][0] + (size_t)h * D * D;
    __half* ol = g_wT[which][1] + (size_t)h * D * D;
    for (int idx = threadIdx.x; idx < D * D; idx += 256) {
        int dout = idx >> 7, f = idx & 127;
        float v = W[(size_t)f * D + dout];
        __half hh = __float2half_rn(v);
        oh[idx] = hh;
        ol[idx] = __float2half_rn(v - __half2float(hh));
    }
}

// ================== qkv via HMMA: grid (32, 8, 3), 256 threads ==================
// smem: WhT[128][136] fp16 | WlT[128][136] fp16  (69632 B); reused as fp32
// transpose buffer [128][133] for the v path.
#define WROW 136
#define QST  (128 * WROW * 2)
#define QSMEM (2 * QST)
#define TP 133

__global__ void __launch_bounds__(256) qkv_mma_kernel() {
    extern __shared__ char sm[];
    const int tid = threadIdx.x, w = tid >> 5, l = tid & 31;
    const int tile = blockIdx.x, h = blockIdx.y, which = blockIdx.z;
    const int lq = l >> 2, lr = l & 3;
    const int n0 = tile * 128;

    // load W^T tiles (hi, lo)
    {
        const uint32_t sb = su32(sm);
        const __half* wh = g_wT[which][0] + (size_t)h * D * D;
        const __half* wl = g_wT[which][1] + (size_t)h * D * D;
        for (int c = tid; c < 2048; c += 256) {
            int r = c >> 4, k = c & 15;
            uint32_t so = (uint32_t)(r * (WROW * 2) + k * 16);
            CP16(sb + so,       wh + (size_t)r * D + k * 8);
            CP16(sb + QST + so, wl + (size_t)r * D + k * 8);
        }
        CPC();
    }

    // x fragments
    uint32_t xa[2][8][4];
#pragma unroll
    for (int s = 0; s < 2; s++) {
        const __half* xs = (s ? g_xl : g_xh) + (size_t)(n0 + w * 16) * D;
#pragma unroll
        for (int j = 0; j < 8; j++) {
            const __half* base = xs + (size_t)lq * D + j * 16 + lr * 2;
            xa[s][j][0] = *(const uint32_t*)(base);
            xa[s][j][1] = *(const uint32_t*)(base + 8 * D);
            xa[s][j][2] = *(const uint32_t*)(base + 8);
            xa[s][j][3] = *(const uint32_t*)(base + 8 * D + 8);
        }
    }

    CPW0();
    __syncthreads();

    const uint32_t* Wh32 = (const uint32_t*)(sm);
    const uint32_t* Wl32 = (const uint32_t*)(sm + QST);

    float s[16][4];
#pragma unroll
    for (int t = 0; t < 16; t++) { s[t][0] = s[t][1] = s[t][2] = s[t][3] = 0.f; }
#pragma unroll
    for (int t = 0; t < 16; t++) {
        int nrow = 8 * t + lq;
#pragma unroll
        for (int j = 0; j < 8; j++) {
            int bi = nrow * (WROW / 2) + j * 8 + lr;
            uint32_t b0 = Wh32[bi], b1 = Wh32[bi + 4];
            uint32_t c0 = Wl32[bi], c1 = Wl32[bi + 4];
            mma(s[t], xa[0][j], b0, b1);
            mma(s[t], xa[1][j], b0, b1);
            mma(s[t], xa[0][j], c0, c1);
        }
    }

    if (which < 2) {
        // q/k: split hi/lo, store row-major
        __half* oh = (which == 0 ? g_qh : g_kh) + ((size_t)h * NT + n0 + w * 16) * D;
        __half* ol = (which == 0 ? g_ql : g_kl) + ((size_t)h * NT + n0 + w * 16) * D;
#pragma unroll
        for (int t = 0; t < 16; t++) {
            int col = 8 * t + lr * 2;
            uint32_t h01, l01, h23, l23;
            pack2(s[t][0], s[t][1], h01, l01);
            pack2(s[t][2], s[t][3], h23, l23);
            *(uint32_t*)(oh + (size_t)lq * D + col)       = h01;
            *(uint32_t*)(ol + (size_t)lq * D + col)       = l01;
            *(uint32_t*)(oh + (size_t)(lq + 8) * D + col) = h23;
            *(uint32_t*)(ol + (size_t)(lq + 8) * D + col) = l23;
        }
    } else {
        // v: transpose via smem, store [h][d][n] fp16 coalesced
        __syncthreads();           // done reading W tiles
        float* buf = (float*)sm;   // [128 tok][133]
#pragma unroll
        for (int t = 0; t < 16; t++) {
            int c = 8 * t + lr * 2;
            int r0 = w * 16 + lq, r1 = r0 + 8;
            buf[r0 * TP + c] = s[t][0]; buf[r0 * TP + c + 1] = s[t][1];
            buf[r1 * TP + c] = s[t][2]; buf[r1 * TP + c + 1] = s[t][3];
        }
        __syncthreads();
#pragma unroll
        for (int dd = 0; dd < 16; dd++) {
            int d = w * 16 + dd;
            int n4 = l * 4;
            __align__(8) __half hb[4];
#pragma unroll
            for (int i = 0; i < 4; i++)
                hb[i] = __float2half_rn(buf[(n4 + i) * TP + d]);
            *(uint2*)(g_vh + ((size_t)h * D + d) * NT + n0 + n4) = *(uint2*)hb;
        }
    }
}

// ---------------- Wg transpose + final MLP --------------------------------------
__global__ void wgT_kernel(const float* __restrict__ Wg) {
    for (int it = threadIdx.x; it < D * D; it += blockDim.x) {
        int d = it >> 7, f = it & 127;
        g_wgT[f * D + d] = Wg[d * D + f];
    }
}

__global__ void __launch_bounds__(256) final_kernel(const float* __restrict__ x,
                                                    const float* __restrict__ bg,
                                                    float* __restrict__ y) {
    __shared__ float hs[64][D];
    __shared__ float Ws[16][D];
    __shared__ float bsh[D];
    const int n0 = blockIdx.x * 64;
    const int tid = threadIdx.x;

    for (int it = tid; it < 64 * 32; it += 256) {
        int r = it >> 5, c4 = it & 31;
        size_t off = (size_t)(n0 + r) * D + c4 * 4;
        float4 a = *(const float4*)(x + off);
#pragma unroll
        for (int hh = 0; hh < H; hh++) {
            float4 b = *(const float4*)(g_o + (size_t)hh * NT * D + off);
            a.x += b.x; a.y += b.y; a.z += b.z; a.w += b.w;
        }
        *(float4*)&hs[r][c4 * 4] = a;
    }
    if (tid < D) bsh[tid] = bg[tid];

    const int ty = tid >> 4, tx = tid & 15;
    float acc[4][8];
#pragma unroll
    for (int i = 0; i < 4; i++)
#pragma unroll
        for (int j = 0; j < 8; j++) acc[i][j] = 0.f;

    for (int fc = 0; fc < 8; fc++) {
        __syncthreads();
        for (int it = tid; it < 16 * 32; it += 256) {
            int r = it >> 5, c4 = it & 31;
            *(float4*)&Ws[r][c4 * 4] = *(const float4*)(g_wgT + (size_t)(fc * 16 + r) * D + c4 * 4);
        }
        __syncthreads();
#pragma unroll
        for (int f = 0; f < 16; f++) {
            float a[4];
#pragma unroll
            for (int ii = 0; ii < 4; ii++) a[ii] = hs[ty * 4 + ii][fc * 16 + f];
            float4 b0 = *(float4*)&Ws[f][tx * 8];
            float4 b1 = *(float4*)&Ws[f][tx * 8 + 4];
            float b[8] = {b0.x, b0.y, b0.z, b0.w, b1.x, b1.y, b1.z, b1.w};
#pragma unroll
            for (int ii = 0; ii < 4; ii++)
#pragma unroll
                for (int jj = 0; jj < 8; jj++)
                    acc[ii][jj] = fmaf(a[ii], b[jj], acc[ii][jj]);
        }
    }

#pragma unroll
    for (int ii = 0; ii < 4; ii++) {
        int n = n0 + ty * 4 + ii;
#pragma unroll
        for (int jj = 0; jj < 8; jj += 4) {
            int d = tx * 8 + jj;
            float4 xv = *(const float4*)(x + (size_t)n * D + d);
            float4 r;
            r.x = xv.x + fmaxf(acc[ii][jj + 0] + bsh[d + 0], 0.f);
            r.y = xv.y + fmaxf(acc[ii][jj + 1] + bsh[d + 1], 0.f);
            r.z = xv.z + fmaxf(acc[ii][jj + 2] + bsh[d + 2], 0.f);
            r.w = xv.w + fmaxf(acc[ii][jj + 3] + bsh[d + 3], 0.f);
            *(float4*)(y + (size_t)n * D + d) = r;
        }
    }
}

// ---------------- launch ---------------------------------------------------------
extern "C" void kernel_launch(void* const* d_in, const int* in_sizes, int n_in,
                              void* d_out, int out_size) {
    const float* x  = (const float*)d_in[0];
    const float* Wk = (const float*)d_in[1];
    const float* Wq = (const float*)d_in[2];
    const float* Wv = (const float*)d_in[3];
    const float* Wm = (const float*)d_in[4];
    const float* Wg = (const float*)d_in[5];
    const float* bg = (const float*)d_in[6];
    float* y = (float*)d_out;

    cudaFuncSetAttribute(attn_kernel, cudaFuncAttributeMaxDynamicSharedMemorySize, ASMEM);
    cudaFuncSetAttribute(qkv_mma_kernel, cudaFuncAttributeMaxDynamicSharedMemorySize, QSMEM);

    splitx_kernel<<<NT * D / (256 * 8), 256>>>(x);
    splitW_kernel<<<dim3(H, 3), 256>>>(Wk, Wq, Wv);
    qkv_mma_kernel<<<dim3(NT / 128, H, 3), 256, QSMEM>>>();
    attn_kernel<<<dim3(NT / 128, H), 256, ASMEM>>>(Wm);
    wgT_kernel<<<1, 256>>>(Wg);
    final_kernel<<<NT / 64, 256>>>(x, bg, y);
}